// round 1
// baseline (speedup 1.0000x reference)
#include <cuda_runtime.h>
#include <cuda_bf16.h>

// LSEP loss, factorized:
//   S_b = (sum_{neg} e^{x}) * (sum_{pos} e^{-x});  loss = mean_b log1p(S_b)
// N = 512 rows, C = 512 cols. One CTA per row, 128 threads, float4/int4 loads.

#define NROWS 512
#define NCOLS 512

__global__ void __launch_bounds__(128) lsep_row_kernel(
    const int* __restrict__ y_true,
    const float* __restrict__ y_pred,
    float* __restrict__ out)
{
    const int row = blockIdx.x;
    const float4* __restrict__ pv = reinterpret_cast<const float4*>(y_pred + row * NCOLS);
    const int4*   __restrict__ tv = reinterpret_cast<const int4*>(y_true + row * NCOLS);

    // 512 cols = 128 float4 -> one vector per thread at blockDim 128
    const int i = threadIdx.x;
    float4 v = pv[i];
    int4   l = tv[i];

    float pos = 0.f, neg = 0.f;

    {
        float fl = (float)l.x;            // label in {0,1}
        float e  = __expf(l.x ? -v.x : v.x);
        pos = fmaf(fl, e, pos);
        neg = fmaf(1.0f - fl, e, neg);
    }
    {
        float fl = (float)l.y;
        float e  = __expf(l.y ? -v.y : v.y);
        pos = fmaf(fl, e, pos);
        neg = fmaf(1.0f - fl, e, neg);
    }
    {
        float fl = (float)l.z;
        float e  = __expf(l.z ? -v.z : v.z);
        pos = fmaf(fl, e, pos);
        neg = fmaf(1.0f - fl, e, neg);
    }
    {
        float fl = (float)l.w;
        float e  = __expf(l.w ? -v.w : v.w);
        pos = fmaf(fl, e, pos);
        neg = fmaf(1.0f - fl, e, neg);
    }

    // warp reduction
    #pragma unroll
    for (int off = 16; off > 0; off >>= 1) {
        pos += __shfl_xor_sync(0xFFFFFFFFu, pos, off);
        neg += __shfl_xor_sync(0xFFFFFFFFu, neg, off);
    }

    __shared__ float s_pos[4];
    __shared__ float s_neg[4];
    const int wid = threadIdx.x >> 5;
    const int lid = threadIdx.x & 31;
    if (lid == 0) { s_pos[wid] = pos; s_neg[wid] = neg; }
    __syncthreads();

    if (threadIdx.x == 0) {
        float p = s_pos[0] + s_pos[1] + s_pos[2] + s_pos[3];
        float n = s_neg[0] + s_neg[1] + s_neg[2] + s_neg[3];
        float contrib = log1pf(p * n) * (1.0f / (float)NROWS);
        atomicAdd(out, contrib);
    }
}

extern "C" void kernel_launch(void* const* d_in, const int* in_sizes, int n_in,
                              void* d_out, int out_size)
{
    const int*   y_true = (const int*)d_in[0];
    const float* y_pred = (const float*)d_in[1];
    float* out = (float*)d_out;

    cudaMemsetAsync(out, 0, sizeof(float), 0);
    lsep_row_kernel<<<NROWS, 128>>>(y_true, y_pred, out);
}